// round 9
// baseline (speedup 1.0000x reference)
#include <cuda_runtime.h>
#include <cuda_bf16.h>
#include <cstdint>

// RotationComponent: w_rotated = w @ rot, a_rotated = x @ rot, rot a
// normalized randomized Hadamard: rot[i,j] = H[i,j] * rot[0,j], H Sylvester,
// rot[0,j] = s_j/64 exactly (s_j = +-1, 1/64 = 2^-6 exact in fp32). Hence
//   (v @ rot)[j] = FWHT(v)[j] * s_j * 2^-6.
//
// Persistent kernel: 888 CTAs (148 SMs x occ 6), each processes rows
// row = bid, bid+888, ... with a 2-stage TMA (cp.async.bulk) pipeline:
// prefetch row j+888 into buf[1-s] while computing row j from buf[s].
// Per-thread column signs packed once into ONE register (16 bits).
//
// FWHT phases (shuffle-free, conflict-free swizzled smem):
//   P1: regs = i-bits {9..6}   i = (t>>6)*1024 + r*64 + (t&63)
//   P2: regs = i-bits {5..2}
//   P3: regs = i-bits {11,10,1,0} -> 4 aligned float4, STG.128
// Swizzle: phys = i ^ ((i>>4) & 28) (16B-granular, preserves LDS.128 blocks).

#define DIM 4096
#define W_ROWS 4096
#define NROWS 12288   // 4096 + 4*2048
#define THREADS 256
#define GRID 888      // 148 * 6
#define ROW_BYTES (DIM * 4)
#define INV64 0.015625f

__device__ __forceinline__ int swz(int i)
{
    return i ^ ((i >> 4) & 28);
}

__device__ __forceinline__ uint32_t smem_u32(const void* p)
{
    uint32_t a;
    asm("{ .reg .u64 t; cvta.to.shared.u64 t, %1; cvt.u32.u64 %0, t; }"
        : "=r"(a) : "l"(p));
    return a;
}

__device__ __forceinline__ void mbar_wait(uint32_t mb, uint32_t parity)
{
    asm volatile(
        "{\n\t"
        ".reg .pred P1;\n\t"
        "WAIT_LOOP_%=:\n\t"
        "mbarrier.try_wait.parity.acquire.cta.shared::cta.b64 P1, [%0], %1, 0x989680;\n\t"
        "@P1 bra.uni WAIT_DONE_%=;\n\t"
        "bra.uni WAIT_LOOP_%=;\n\t"
        "WAIT_DONE_%=:\n\t"
        "}"
        :: "r"(mb), "r"(parity) : "memory");
}

__global__ __launch_bounds__(THREADS, 6)
void fwht_rotate_kernel(const float* __restrict__ w,
                        const float* __restrict__ x,
                        const float* __restrict__ rot,
                        float* __restrict__ out)
{
    __shared__ float buf[2][DIM];
    __shared__ __align__(8) unsigned long long mbar[2];

    const int t    = threadIdx.x;
    const int lane = t & 31;
    const int warp = t >> 5;

    const uint32_t mb0 = smem_u32(&mbar[0]);
    const uint32_t mb1 = smem_u32(&mbar[1]);

    if (t == 0) {
        asm volatile("mbarrier.init.shared.b64 [%0], 1;" :: "r"(mb0) : "memory");
        asm volatile("mbarrier.init.shared.b64 [%0], 1;" :: "r"(mb1) : "memory");
    }

    // ---- Pack per-thread column signs (16 bits) from rot row 0, once ----
    const int p3_base = t * 4;
    unsigned mask = 0;
    #pragma unroll
    for (int c = 0; c < 4; c++) {
        float4 sv = __ldg((const float4*)(rot + c * 1024 + p3_base));
        mask |= (__float_as_uint(sv.x) >> 31) << (c * 4 + 0);
        mask |= (__float_as_uint(sv.y) >> 31) << (c * 4 + 1);
        mask |= (__float_as_uint(sv.z) >> 31) << (c * 4 + 2);
        mask |= (__float_as_uint(sv.w) >> 31) << (c * 4 + 3);
    }
    __syncthreads();

    const int p1_base = (t >> 6) * 1024 + (t & 63);
    const int p2_base = (warp * 8 + ((lane >> 2) & 7)) * 64 + (lane & 3);

    // ---- Prologue: prefetch first row into buf[0] ----
    int row = blockIdx.x;
    if (t == 0 && row < NROWS) {
        const float* src = (row < W_ROWS) ? (w + (size_t)row * DIM)
                                          : (x + (size_t)(row - W_ROWS) * DIM);
        asm volatile("mbarrier.arrive.expect_tx.shared.b64 _, [%0], %1;"
                     :: "r"(mb0), "r"((uint32_t)ROW_BYTES) : "memory");
        asm volatile("cp.async.bulk.shared::cta.global.mbarrier::complete_tx::bytes "
                     "[%0], [%1], %2, [%3];"
                     :: "r"(smem_u32(buf[0])), "l"(src),
                        "r"((uint32_t)ROW_BYTES), "r"(mb0) : "memory");
    }

    int s = 0;
    unsigned parity0 = 0, parity1 = 0;

    for (; row < NROWS; row += GRID) {
        // ---- Prefetch next row into buf[1-s] (safe: prior use synced) ----
        const int nrow = row + GRID;
        if (t == 0 && nrow < NROWS) {
            const float* nsrc = (nrow < W_ROWS)
                ? (w + (size_t)nrow * DIM)
                : (x + (size_t)(nrow - W_ROWS) * DIM);
            const uint32_t nmb = s ? mb0 : mb1;
            asm volatile("mbarrier.arrive.expect_tx.shared.b64 _, [%0], %1;"
                         :: "r"(nmb), "r"((uint32_t)ROW_BYTES) : "memory");
            asm volatile("cp.async.bulk.shared::cta.global.mbarrier::complete_tx::bytes "
                         "[%0], [%1], %2, [%3];"
                         :: "r"(smem_u32(buf[1 - s])), "l"(nsrc),
                            "r"((uint32_t)ROW_BYTES), "r"(nmb) : "memory");
        }

        // ---- Wait for current row ----
        if (s == 0) { mbar_wait(mb0, parity0); parity0 ^= 1; }
        else        { mbar_wait(mb1, parity1); parity1 ^= 1; }

        float* b = buf[s];
        float v[16];

        // ---- P1: linear read; butterflies on i-bits {9..6} ----
        #pragma unroll
        for (int r = 0; r < 16; r++) {
            v[r] = b[p1_base + r * 64];
        }
        #pragma unroll
        for (int m = 8; m >= 1; m >>= 1) {
            #pragma unroll
            for (int r = 0; r < 16; r++) {
                if ((r & m) == 0) {
                    float a = v[r], bb = v[r | m];
                    v[r]     = a + bb;
                    v[r | m] = a - bb;
                }
            }
        }
        __syncthreads();   // in-place reuse: all P1 reads done

        // ---- T1: swizzled write ----
        #pragma unroll
        for (int r = 0; r < 16; r++) {
            b[swz(p1_base + r * 64)] = v[r];
        }
        __syncthreads();

        // ---- P2: butterflies on i-bits {5..2} ----
        #pragma unroll
        for (int r = 0; r < 16; r++) {
            v[r] = b[swz(p2_base + r * 4)];
        }
        #pragma unroll
        for (int m = 8; m >= 1; m >>= 1) {
            #pragma unroll
            for (int r = 0; r < 16; r++) {
                if ((r & m) == 0) {
                    float a = v[r], bb = v[r | m];
                    v[r]     = a + bb;
                    v[r | m] = a - bb;
                }
            }
        }
        #pragma unroll
        for (int r = 0; r < 16; r++) {
            b[swz(p2_base + r * 4)] = v[r];
        }
        __syncthreads();

        // ---- P3: LDS.128; butterflies on i-bits {11,10,1,0} ----
        #pragma unroll
        for (int c = 0; c < 4; c++) {
            float4 q = *(const float4*)(b + swz(c * 1024 + p3_base));
            v[c * 4 + 0] = q.x;
            v[c * 4 + 1] = q.y;
            v[c * 4 + 2] = q.z;
            v[c * 4 + 3] = q.w;
        }
        #pragma unroll
        for (int m = 8; m >= 1; m >>= 1) {
            #pragma unroll
            for (int r = 0; r < 16; r++) {
                if ((r & m) == 0) {
                    float a = v[r], bb = v[r | m];
                    v[r]     = a + bb;
                    v[r | m] = a - bb;
                }
            }
        }
        __syncthreads();   // all P3 reads done -> buf[s] free for prefetch next iter

        // ---- Epilogue: apply sign via XOR, scale by exact 2^-6, STG.128 ----
        float* dst = out + (size_t)row * DIM;
        #pragma unroll
        for (int c = 0; c < 4; c++) {
            float4 o;
            #pragma unroll
            for (int e = 0; e < 4; e++) {
                const int k = c * 4 + e;
                unsigned sb = ((mask >> k) << 31);
                float sv = __int_as_float(__float_as_int(v[k]) ^ (int)sb) * INV64;
                ((float*)&o)[e] = sv;
            }
            *(float4*)(dst + c * 1024 + p3_base) = o;
        }

        s ^= 1;
    }
}

extern "C" void kernel_launch(void* const* d_in, const int* in_sizes, int n_in,
                              void* d_out, int out_size)
{
    const float* w   = (const float*)d_in[0];   // [4096, 4096]
    const float* x   = (const float*)d_in[1];   // [4, 2048, 4096]
    const float* rot = (const float*)d_in[2];   // [4096, 4096]
    float* out = (float*)d_out;                 // w_rotated then a_rotated

    (void)in_sizes; (void)n_in; (void)out_size;

    fwht_rotate_kernel<<<GRID, THREADS>>>(w, x, rot, out);
}

// round 10
// speedup vs baseline: 1.1197x; 1.1197x over previous
#include <cuda_runtime.h>
#include <cuda_bf16.h>
#include <cstdint>

// RotationComponent: w_rotated = w @ rot, a_rotated = x @ rot, rot a
// normalized randomized Hadamard: rot[i,j] = H[i,j] * rot[0,j], H Sylvester,
// rot[0,j] = s_j * 2^-6 exactly (s_j = +-1). Hence
//   (v @ rot)[j] = FWHT(v)[j] * s_j * 2^-6.
//
// One CTA per row (12288 single-shot CTAs). Input row arrives via ONE
// cp.async.bulk (TMA) 16KB copy + mbarrier (no per-warp LDG burst, so the
// L1tex-queue contention that penalized high occupancy in the LDG variant
// does not apply). __launch_bounds__(256, 8) -> 32 regs, 8 CTAs/SM.
// Per-thread column signs packed into ONE register in the prologue (the rot
// LDGs overlap the TMA wait); epilogue is sign-XOR + multiply by exact 2^-6.
//
// FWHT phases (shuffle-free, conflict-free swizzled smem):
//   P1: regs = i-bits {9..6}   i = (t>>6)*1024 + r*64 + (t&63)
//   P2: regs = i-bits {5..2}   i = J*64 + r*4 + e2
//   P3: regs = i-bits {11,10,1,0} -> 4 aligned float4, STG.128
// Swizzle: phys = i ^ ((i>>4) & 28) (16B-granular, preserves LDS.128 blocks).

#define DIM 4096
#define W_ROWS 4096
#define THREADS 256
#define ROW_BYTES (DIM * 4)
#define INV64 0.015625f

__device__ __forceinline__ int swz(int i)
{
    return i ^ ((i >> 4) & 28);
}

__device__ __forceinline__ uint32_t smem_u32(const void* p)
{
    uint32_t a;
    asm("{ .reg .u64 t; cvta.to.shared.u64 t, %1; cvt.u32.u64 %0, t; }"
        : "=r"(a) : "l"(p));
    return a;
}

__global__ __launch_bounds__(THREADS, 8)
void fwht_rotate_kernel(const float* __restrict__ w,
                        const float* __restrict__ x,
                        const float* __restrict__ rot,
                        float* __restrict__ out)
{
    __shared__ float buf[DIM];
    __shared__ __align__(8) unsigned long long mbar;

    const int row  = blockIdx.x;
    const int t    = threadIdx.x;
    const int lane = t & 31;
    const int warp = t >> 5;

    const float* src = (row < W_ROWS)
        ? (w + (size_t)row * DIM)
        : (x + (size_t)(row - W_ROWS) * DIM);

    const uint32_t mb = smem_u32(&mbar);

    // ---- Kick off TMA bulk load ASAP ----
    if (t == 0) {
        asm volatile("mbarrier.init.shared.b64 [%0], 1;" :: "r"(mb) : "memory");
        // fence init before the TMA engine can signal this barrier
        asm volatile("fence.proxy.async.shared::cta;" ::: "memory");
        asm volatile("mbarrier.arrive.expect_tx.shared.b64 _, [%0], %1;"
                     :: "r"(mb), "r"((uint32_t)ROW_BYTES) : "memory");
        asm volatile("cp.async.bulk.shared::cta.global.mbarrier::complete_tx::bytes "
                     "[%0], [%1], %2, [%3];"
                     :: "r"(smem_u32(buf)), "l"(src),
                        "r"((uint32_t)ROW_BYTES), "r"(mb)
                     : "memory");
    }

    // ---- Overlap: pack per-thread column signs from rot row 0 (L1-hit) ----
    const int p3_base = t * 4;
    unsigned mask = 0;
    #pragma unroll
    for (int c = 0; c < 4; c++) {
        float4 sv = __ldg((const float4*)(rot + c * 1024 + p3_base));
        mask |= (__float_as_uint(sv.x) >> 31) << (c * 4 + 0);
        mask |= (__float_as_uint(sv.y) >> 31) << (c * 4 + 1);
        mask |= (__float_as_uint(sv.z) >> 31) << (c * 4 + 2);
        mask |= (__float_as_uint(sv.w) >> 31) << (c * 4 + 3);
    }

    // ---- __syncthreads so every thread sees the initialized barrier, then
    //      wait for TMA completion (parity 0, HW sleep) ----
    __syncthreads();
    asm volatile(
        "{\n\t"
        ".reg .pred P1;\n\t"
        "WAIT_LOOP_%=:\n\t"
        "mbarrier.try_wait.parity.acquire.cta.shared::cta.b64 P1, [%0], 0, 0x989680;\n\t"
        "@P1 bra.uni WAIT_DONE_%=;\n\t"
        "bra.uni WAIT_LOOP_%=;\n\t"
        "WAIT_DONE_%=:\n\t"
        "}"
        :: "r"(mb) : "memory");

    float v[16];

    // ---- P1: linear read; butterflies on i-bits {9..6} ----
    const int p1_base = (t >> 6) * 1024 + (t & 63);
    #pragma unroll
    for (int r = 0; r < 16; r++) {
        v[r] = buf[p1_base + r * 64];
    }
    #pragma unroll
    for (int m = 8; m >= 1; m >>= 1) {
        #pragma unroll
        for (int r = 0; r < 16; r++) {
            if ((r & m) == 0) {
                float a = v[r], b = v[r | m];
                v[r]     = a + b;
                v[r | m] = a - b;
            }
        }
    }
    __syncthreads();   // in-place reuse: all P1 reads done

    // ---- T1: swizzled write ----
    #pragma unroll
    for (int r = 0; r < 16; r++) {
        buf[swz(p1_base + r * 64)] = v[r];
    }
    __syncthreads();

    // ---- P2: butterflies on i-bits {5..2} ----
    const int p2_base = (warp * 8 + ((lane >> 2) & 7)) * 64 + (lane & 3);
    #pragma unroll
    for (int r = 0; r < 16; r++) {
        v[r] = buf[swz(p2_base + r * 4)];
    }
    #pragma unroll
    for (int m = 8; m >= 1; m >>= 1) {
        #pragma unroll
        for (int r = 0; r < 16; r++) {
            if ((r & m) == 0) {
                float a = v[r], b = v[r | m];
                v[r]     = a + b;
                v[r | m] = a - b;
            }
        }
    }
    #pragma unroll
    for (int r = 0; r < 16; r++) {
        buf[swz(p2_base + r * 4)] = v[r];
    }
    __syncthreads();

    // ---- P3: LDS.128; butterflies on i-bits {11,10,1,0} ----
    #pragma unroll
    for (int c = 0; c < 4; c++) {
        float4 q = *(const float4*)(buf + swz(c * 1024 + p3_base));
        v[c * 4 + 0] = q.x;
        v[c * 4 + 1] = q.y;
        v[c * 4 + 2] = q.z;
        v[c * 4 + 3] = q.w;
    }
    #pragma unroll
    for (int m = 8; m >= 1; m >>= 1) {
        #pragma unroll
        for (int r = 0; r < 16; r++) {
            if ((r & m) == 0) {
                float a = v[r], b = v[r | m];
                v[r]     = a + b;
                v[r | m] = a - b;
            }
        }
    }

    // ---- Epilogue: sign-XOR + exact 2^-6 scale, 4x STG.128 ----
    float* dst = out + (size_t)row * DIM;
    #pragma unroll
    for (int c = 0; c < 4; c++) {
        float4 o;
        #pragma unroll
        for (int e = 0; e < 4; e++) {
            const int k = c * 4 + e;
            const unsigned sb = (mask >> k) << 31;
            ((float*)&o)[e] =
                __int_as_float(__float_as_int(v[k]) ^ (int)sb) * INV64;
        }
        *(float4*)(dst + c * 1024 + p3_base) = o;
    }
}

extern "C" void kernel_launch(void* const* d_in, const int* in_sizes, int n_in,
                              void* d_out, int out_size)
{
    const float* w   = (const float*)d_in[0];   // [4096, 4096]
    const float* x   = (const float*)d_in[1];   // [4, 2048, 4096]
    const float* rot = (const float*)d_in[2];   // [4096, 4096]
    float* out = (float*)d_out;                 // w_rotated then a_rotated

    (void)in_sizes; (void)n_in; (void)out_size;

    fwht_rotate_kernel<<<12288, THREADS>>>(w, x, rot, out);
}